// round 11
// baseline (speedup 1.0000x reference)
#include <cuda_runtime.h>
#include <cstdint>

// AggregateLevels: FPN anchor decode, 5 levels fused. B=16, A=261888.
// cp.async per-thread pipeline: each thread owns its smem slots, so no
// __syncthreads is needed. 4-stage ring, 3 stages in flight, 8 pos/thread.
// All loads/stores warp-contiguous (1 position per thread per iteration).
// Output (float32): scores [B,A,2] @0 ; boxes [B,A,4] @B*A*2 ; anchors [B,A,4] @B*A*6.

#define B_SZ    16
#define A_TOT   261888
#define TPB     256
#define NPOS    8
#define STAGES  4
#define GRIDX   128          // 128 * 2048 = 262144 >= A_TOT

__constant__ int   c_off[5]   = {0, 196608, 245760, 258048, 261120};
__constant__ int   c_lghw[5]  = {16, 14, 12, 10, 8};
__constant__ int   c_lgw[5]   = {8, 7, 6, 5, 4};
__constant__ float c_scale[5] = {4.f, 8.f, 16.f, 32.f, 64.f};
__constant__ float c_half[5]  = {1.5f, 3.5f, 7.5f, 15.5f, 31.5f};
__constant__ float c_anch[5]  = {0.0625f, 0.125f, 0.25f, 0.5f, 1.0f}; // 2^(i-6)

struct Ptrs {
    const float* cs[5];
    const float* bp[5];
    const int*   ih;
    const int*   iw;
};

__device__ __forceinline__ void cp_async4(uint32_t smem_addr, const float* gptr) {
    asm volatile("cp.async.ca.shared.global [%0], [%1], 4;\n"
                 :: "r"(smem_addr), "l"(gptr));
}
__device__ __forceinline__ void cp_commit() {
    asm volatile("cp.async.commit_group;\n");
}
__device__ __forceinline__ void cp_wait2() {
    asm volatile("cp.async.wait_group %0;\n" :: "n"(STAGES - 2));
}

struct Dec {
    int lv, a, rem, lghw, hw, x, y;
};

__device__ __forceinline__ Dec decode(int pp) {
    Dec d;
    d.lv   = (pp >= 196608) + (pp >= 245760) + (pp >= 258048) + (pp >= 261120);
    const int q = pp - c_off[d.lv];
    d.lghw = c_lghw[d.lv];
    d.hw   = 1 << d.lghw;
    d.a    = q >> d.lghw;
    d.rem  = q & (d.hw - 1);
    const int lgw = c_lgw[d.lv];
    d.y    = d.rem >> lgw;
    d.x    = d.rem & ((1 << lgw) - 1);
    return d;
}

__global__ __launch_bounds__(TPB)
void aggregate_levels_kernel(Ptrs ptrs, float* __restrict__ out) {
    __shared__ float sm[STAGES][6][TPB];

    const int tid  = threadIdx.x;
    const int b    = blockIdx.y;
    const int base = blockIdx.x * (TPB * NPOS) + tid;

    const float fih = (float)(*ptrs.ih);
    const float fiw = (float)(*ptrs.iw);

    // smem byte addresses of this thread's 6 slots per stage
    uint32_t sbase = (uint32_t)__cvta_generic_to_shared(&sm[0][0][tid]);

    // issue 6 cp.asyncs for iteration it into stage it%STAGES
    auto issue = [&](int it) {
        const int p  = base + it * TPB;
        const int pp = (p < A_TOT) ? p : 0;
        const Dec d  = decode(pp);
        const float* cs = ptrs.cs[d.lv] + (((b * 6  + d.a * 2) << d.lghw) + d.rem);
        const float* bp = ptrs.bp[d.lv] + (((b * 12 + d.a * 4) << d.lghw) + d.rem);
        const uint32_t s = sbase + (uint32_t)((it & (STAGES - 1)) * 6 * TPB * 4);
        cp_async4(s + 0 * TPB * 4, cs);
        cp_async4(s + 1 * TPB * 4, cs + d.hw);
        cp_async4(s + 2 * TPB * 4, bp);
        cp_async4(s + 3 * TPB * 4, bp + d.hw);
        cp_async4(s + 4 * TPB * 4, bp + 2 * d.hw);
        cp_async4(s + 5 * TPB * 4, bp + 3 * d.hw);
    };

    // prologue: 3 stages in flight
    issue(0); cp_commit();
    issue(1); cp_commit();
    issue(2); cp_commit();

    float2* os = reinterpret_cast<float2*>(out);
    float4* ob = reinterpret_cast<float4*>(out + (size_t)B_SZ * A_TOT * 2);
    float4* oa = reinterpret_cast<float4*>(out + (size_t)B_SZ * A_TOT * 6);

    #pragma unroll
    for (int it = 0; it < NPOS; ++it) {
        cp_wait2();     // stage `it` complete (only this thread's own slots read)

        const int st = it & (STAGES - 1);
        const float c0 = sm[st][0][tid];
        const float c1 = sm[st][1][tid];
        const float d0 = sm[st][2][tid];
        const float d1 = sm[st][3][tid];
        const float d2 = sm[st][4][tid];
        const float d3 = sm[st][5][tid];

        // refill pipeline before compute
        const int nx = it + (STAGES - 1);
        if (nx < NPOS) issue(nx);
        cp_commit();    // always commit to keep group counting uniform

        const int p  = base + it * TPB;
        if (p < A_TOT) {
            const Dec d = decode(p);
            const float s    = c_scale[d.lv];
            const float hc   = c_half[d.lv];
            const float an   = c_anch[d.lv];
            const float a_cy = s * (float)d.y + hc;
            const float a_cx = s * (float)d.x + hc;
            const float ha   = fih * an;
            const float wa   = fiw * an;
            const float a_h  = (d.a == 2) ? 2.0f * ha : ha;   // {ha, ha, 2ha}
            const float a_w  = (d.a == 0) ? 2.0f * wa : wa;   // {2wa, wa, wa}

            const float cyc = a_cy + d0 * a_h;
            const float cxc = a_cx + d1 * a_w;
            const float hh  = a_h * __expf(d2);
            const float ww  = a_w * __expf(d3);

            const float y1 = fminf(fmaxf(cyc - 0.5f * hh, 0.0f), fih);
            const float x1 = fminf(fmaxf(cxc - 0.5f * ww, 0.0f), fiw);
            const float y2 = fminf(fmaxf(cyc + 0.5f * hh, 0.0f), fih);
            const float x2 = fminf(fmaxf(cxc + 0.5f * ww, 0.0f), fiw);

            const size_t idx = (size_t)b * A_TOT + p;
            __stcs(os + idx, make_float2(c0, c1));
            __stcs(ob + idx, make_float4(y1, x1, y2, x2));
            __stcs(oa + idx, make_float4(a_cy, a_cx, a_h, a_w));
        }
    }
}

extern "C" void kernel_launch(void* const* d_in, const int* in_sizes, int n_in,
                              void* d_out, int out_size) {
    (void)out_size;
    // Identify inputs by element count (robust to metadata ordering).
    Ptrs ptrs;
    ptrs.ih = nullptr; ptrs.iw = nullptr;
    for (int i = 0; i < n_in; ++i) {
        const long long sz = in_sizes[i];
        if (sz == 1) {
            if (!ptrs.ih) ptrs.ih = (const int*)d_in[i];
            else          ptrs.iw = (const int*)d_in[i];
            continue;
        }
        for (int l = 0; l < 5; ++l) {
            const long long hw = 65536LL >> (2 * l);
            if (sz == 16LL * 6 * hw)  ptrs.cs[l] = (const float*)d_in[i];
            if (sz == 16LL * 12 * hw) ptrs.bp[l] = (const float*)d_in[i];
        }
    }

    dim3 grid(GRIDX, B_SZ);
    aggregate_levels_kernel<<<grid, TPB>>>(ptrs, (float*)d_out);
}

// round 14
// speedup vs baseline: 1.1548x; 1.1548x over previous
#include <cuda_runtime.h>
#include <cstdint>

// AggregateLevels via bulk-async (TMA) both directions.
// Each CTA: one contiguous chunk of positions within a single (b, level, aspect)
// plane. 6 cp.async.bulk loads (cs pair + 4 bp planes) -> smem, compute,
// stage outputs in smem, 3 cp.async.bulk stores -> out.
// B=16, A=261888. Levels i=2..6: hw = 65536,16384,4096,1024,256.
// Chunks/batch (TILE=512): l0:384  l1:96  l2:24  l3:6  l4:3(n=256)  => 513.
// Output (float32): scores [B,A,2] @0 ; boxes [B,A,4] @B*A*2 ; anchors [B,A,4] @B*A*6.

#define B_SZ   16
#define A_TOT  261888
#define TPB    256
#define TILE   512
#define NCHUNK 513

__constant__ int   c_off[5]   = {0, 196608, 245760, 258048, 261120};
__constant__ int   c_lghw[5]  = {16, 14, 12, 10, 8};
__constant__ int   c_lgw[5]   = {8, 7, 6, 5, 4};
__constant__ float c_scale[5] = {4.f, 8.f, 16.f, 32.f, 64.f};
__constant__ float c_half[5]  = {1.5f, 3.5f, 7.5f, 15.5f, 31.5f};
__constant__ float c_anch[5]  = {0.0625f, 0.125f, 0.25f, 0.5f, 1.0f}; // 2^(i-6)

struct Ptrs {
    const float* cs[5];
    const float* bp[5];
    const int*   ih;
    const int*   iw;
};

__device__ __forceinline__ uint32_t smem_u32(const void* p) {
    return (uint32_t)__cvta_generic_to_shared(p);
}

__global__ __launch_bounds__(TPB)
void aggregate_levels_kernel(Ptrs ptrs, float* __restrict__ out) {
    __shared__ __align__(16) float s_in[6][TILE];     // c0,c1,d0,d1,d2,d3
    __shared__ __align__(16) float s_sc[2 * TILE];
    __shared__ __align__(16) float s_box[4 * TILE];
    __shared__ __align__(16) float s_anc[4 * TILE];
    __shared__ __align__(8)  unsigned long long s_mbar;

    const int tid = threadIdx.x;
    const int b   = blockIdx.y;
    const int c   = blockIdx.x;

    // ---- chunk decode ----
    int l, a, start, n;
    if (c < 384)      { l = 0; a = c >> 7;                    start = (c & 127) << 9; n = TILE; }
    else if (c < 480) { l = 1; int t = c - 384; a = t >> 5;   start = (t & 31) << 9;  n = TILE; }
    else if (c < 504) { l = 2; int t = c - 480; a = t >> 3;   start = (t & 7) << 9;   n = TILE; }
    else if (c < 510) { l = 3; int t = c - 504; a = t >> 1;   start = (t & 1) << 9;   n = TILE; }
    else              { l = 4; a = c - 510;                   start = 0;              n = 256;  }

    const int lghw = c_lghw[l];
    const int hw   = 1 << lghw;
    const int lgw  = c_lgw[l];
    const int nb   = n * 4;                         // bytes per plane slice

    const float* cs_base = ptrs.cs[l] + (((b * 6  + a * 2) << lghw) + start);
    const float* bp_base = ptrs.bp[l] + (((b * 12 + a * 4) << lghw) + start);

    const uint32_t mbar = smem_u32(&s_mbar);

    if (tid == 0) {
        asm volatile("mbarrier.init.shared.b64 [%0], %1;" :: "r"(mbar), "r"(1u));
    }
    __syncthreads();

    if (tid == 0) {
        asm volatile("mbarrier.arrive.expect_tx.shared.b64 _, [%0], %1;"
                     :: "r"(mbar), "r"(6u * nb));
        const float* srcs[6] = {cs_base, cs_base + hw,
                                bp_base, bp_base + hw, bp_base + 2 * hw, bp_base + 3 * hw};
        #pragma unroll
        for (int j = 0; j < 6; ++j) {
            asm volatile(
                "cp.async.bulk.shared::cluster.global.mbarrier::complete_tx::bytes "
                "[%0], [%1], %2, [%3];"
                :: "r"(smem_u32(&s_in[j][0])), "l"(srcs[j]), "r"(nb), "r"(mbar)
                : "memory");
        }
    }

    // wait phase 0 (acquire so following LDS sees TMA data)
    {
        uint32_t done;
        do {
            asm volatile(
                "{\n\t.reg .pred p;\n\t"
                "mbarrier.try_wait.parity.acquire.cta.shared::cta.b64 p, [%1], %2;\n\t"
                "selp.b32 %0, 1, 0, p;\n\t}"
                : "=r"(done) : "r"(mbar), "r"(0u) : "memory");
        } while (!done);
    }

    // ---- compute ----
    const float fih = (float)(*ptrs.ih);
    const float fiw = (float)(*ptrs.iw);
    const float s    = c_scale[l];
    const float hc   = c_half[l];
    const float an   = c_anch[l];
    const float ha   = fih * an;
    const float wa   = fiw * an;
    const float a_h  = (a == 2) ? 2.0f * ha : ha;   // hs = {ha, ha, 2ha}
    const float a_w  = (a == 0) ? 2.0f * wa : wa;   // ws = {2wa, wa, wa}

    for (int i = tid; i < n; i += TPB) {
        const int rem = start + i;
        const int y   = rem >> lgw;
        const int x   = rem & ((1 << lgw) - 1);
        const float a_cy = s * (float)y + hc;
        const float a_cx = s * (float)x + hc;

        const float c0 = s_in[0][i];
        const float c1 = s_in[1][i];
        const float d0 = s_in[2][i];
        const float d1 = s_in[3][i];
        const float d2 = s_in[4][i];
        const float d3 = s_in[5][i];

        const float cyc = a_cy + d0 * a_h;
        const float cxc = a_cx + d1 * a_w;
        const float hh  = a_h * __expf(d2);
        const float ww  = a_w * __expf(d3);

        const float y1 = fminf(fmaxf(cyc - 0.5f * hh, 0.0f), fih);
        const float x1 = fminf(fmaxf(cxc - 0.5f * ww, 0.0f), fiw);
        const float y2 = fminf(fmaxf(cyc + 0.5f * hh, 0.0f), fih);
        const float x2 = fminf(fmaxf(cxc + 0.5f * ww, 0.0f), fiw);

        reinterpret_cast<float2*>(s_sc)[i]  = make_float2(c0, c1);
        reinterpret_cast<float4*>(s_box)[i] = make_float4(y1, x1, y2, x2);
        reinterpret_cast<float4*>(s_anc)[i] = make_float4(a_cy, a_cx, a_h, a_w);
    }
    __syncthreads();

    // ---- bulk stores ----
    if (tid == 0) {
        asm volatile("fence.proxy.async.shared::cta;" ::: "memory");

        const size_t p_base = (size_t)c_off[l] + (size_t)a * hw + start;
        const size_t idx    = (size_t)b * A_TOT + p_base;
        float* g_sc  = out + idx * 2;
        float* g_box = out + (size_t)B_SZ * A_TOT * 2 + idx * 4;
        float* g_anc = out + (size_t)B_SZ * A_TOT * 6 + idx * 4;

        asm volatile("cp.async.bulk.global.shared::cta.bulk_group [%0], [%1], %2;"
                     :: "l"(g_sc),  "r"(smem_u32(s_sc)),  "r"(2u * nb) : "memory");
        asm volatile("cp.async.bulk.global.shared::cta.bulk_group [%0], [%1], %2;"
                     :: "l"(g_box), "r"(smem_u32(s_box)), "r"(4u * nb) : "memory");
        asm volatile("cp.async.bulk.global.shared::cta.bulk_group [%0], [%1], %2;"
                     :: "l"(g_anc), "r"(smem_u32(s_anc)), "r"(4u * nb) : "memory");
        asm volatile("cp.async.bulk.commit_group;");
        asm volatile("cp.async.bulk.wait_group 0;" ::: "memory");
    }
}

extern "C" void kernel_launch(void* const* d_in, const int* in_sizes, int n_in,
                              void* d_out, int out_size) {
    (void)out_size;
    // Identify inputs by element count (robust to metadata ordering).
    Ptrs ptrs;
    ptrs.ih = nullptr; ptrs.iw = nullptr;
    for (int i = 0; i < n_in; ++i) {
        const long long sz = in_sizes[i];
        if (sz == 1) {
            if (!ptrs.ih) ptrs.ih = (const int*)d_in[i];
            else          ptrs.iw = (const int*)d_in[i];
            continue;
        }
        for (int l = 0; l < 5; ++l) {
            const long long hw = 65536LL >> (2 * l);
            if (sz == 16LL * 6 * hw)  ptrs.cs[l] = (const float*)d_in[i];
            if (sz == 16LL * 12 * hw) ptrs.bp[l] = (const float*)d_in[i];
        }
    }

    dim3 grid(NCHUNK, B_SZ);
    aggregate_levels_kernel<<<grid, TPB>>>(ptrs, (float*)d_out);
}

// round 15
// speedup vs baseline: 1.3058x; 1.1308x over previous
#include <cuda_runtime.h>
#include <cstdint>

// AggregateLevels: FPN anchor generation + delta decode, 5 levels fused.
// B=16, IH=IW=1024. A = 261888 = 1023*256 (exact grid, no bounds checks).
// ILP across BATCHES: each thread owns one position p and 4 batches.
// - identical memory pattern to the best LDG version (fully coalesced,
//   24 independent loads in flight per thread)
// - level/position decode and anchor math computed ONCE per thread
// Output (float32): scores [B,A,2] @0 ; boxes [B,A,4] @B*A*2 ; anchors [B,A,4] @B*A*6.

#define B_SZ   16
#define A_TOT  261888
#define TPB    256
#define KB     4            // batches per thread

__constant__ int   c_off[5]   = {0, 196608, 245760, 258048, 261120};
__constant__ int   c_lghw[5]  = {16, 14, 12, 10, 8};
__constant__ int   c_lgw[5]   = {8, 7, 6, 5, 4};
__constant__ float c_scale[5] = {4.f, 8.f, 16.f, 32.f, 64.f};
__constant__ float c_half[5]  = {1.5f, 3.5f, 7.5f, 15.5f, 31.5f};
__constant__ float c_anch[5]  = {0.0625f, 0.125f, 0.25f, 0.5f, 1.0f}; // 2^(i-6)

struct Ptrs {
    const float* cs[5];
    const float* bp[5];
    const int*   ih;
    const int*   iw;
};

__global__ __launch_bounds__(TPB)
void aggregate_levels_kernel(Ptrs ptrs, float* __restrict__ out) {
    const int p  = blockIdx.x * TPB + threadIdx.x;   // < A_TOT always (1023*256)
    const int b0 = blockIdx.y * KB;

    // ---- decode ONCE per thread ----
    const int lv   = (p >= 196608) + (p >= 245760) + (p >= 258048) + (p >= 261120);
    const int q    = p - c_off[lv];
    const int lghw = c_lghw[lv];
    const int hw   = 1 << lghw;
    const int a    = q >> lghw;            // aspect 0..2
    const int rem  = q & (hw - 1);
    const int lgw  = c_lgw[lv];
    const int y    = rem >> lgw;
    const int x    = rem & ((1 << lgw) - 1);

    const float fih = (float)(*ptrs.ih);
    const float fiw = (float)(*ptrs.iw);

    const float s    = c_scale[lv];
    const float hc   = c_half[lv];
    const float an   = c_anch[lv];
    const float a_cy = s * (float)y + hc;
    const float a_cx = s * (float)x + hc;
    const float ha   = fih * an;
    const float wa   = fiw * an;
    const float a_h  = (a == 2) ? 2.0f * ha : ha;   // hs = {ha, ha, 2ha}
    const float a_w  = (a == 0) ? 2.0f * wa : wa;   // ws = {2wa, wa, wa}

    // ---- issue ALL 24 loads (4 batches x 6 planes) before any consumption ----
    const float* cs0 = ptrs.cs[lv] + (((b0 * 6  + a * 2) << lghw) + rem);
    const float* bp0 = ptrs.bp[lv] + (((b0 * 12 + a * 4) << lghw) + rem);
    const int cs_str = 6  << lghw;          // per-batch stride in cs
    const int bp_str = 12 << lghw;          // per-batch stride in bp

    float c0[KB], c1[KB], d0[KB], d1[KB], d2[KB], d3[KB];
    #pragma unroll
    for (int k = 0; k < KB; ++k) {
        const float* cs = cs0 + k * cs_str;
        const float* bp = bp0 + k * bp_str;
        c0[k] = __ldcs(cs);
        c1[k] = __ldcs(cs + hw);
        d0[k] = __ldcs(bp);
        d1[k] = __ldcs(bp + hw);
        d2[k] = __ldcs(bp + 2 * hw);
        d3[k] = __ldcs(bp + 3 * hw);
    }

    // ---- compute + store ----
    float2* os = reinterpret_cast<float2*>(out);
    float4* ob = reinterpret_cast<float4*>(out + (size_t)B_SZ * A_TOT * 2);
    float4* oa = reinterpret_cast<float4*>(out + (size_t)B_SZ * A_TOT * 6);
    const float4 anc = make_float4(a_cy, a_cx, a_h, a_w);

    #pragma unroll
    for (int k = 0; k < KB; ++k) {
        const float cyc = a_cy + d0[k] * a_h;
        const float cxc = a_cx + d1[k] * a_w;
        const float hh  = a_h * __expf(d2[k]);
        const float ww  = a_w * __expf(d3[k]);

        const float y1 = fminf(fmaxf(cyc - 0.5f * hh, 0.0f), fih);
        const float x1 = fminf(fmaxf(cxc - 0.5f * ww, 0.0f), fiw);
        const float y2 = fminf(fmaxf(cyc + 0.5f * hh, 0.0f), fih);
        const float x2 = fminf(fmaxf(cxc + 0.5f * ww, 0.0f), fiw);

        const size_t idx = (size_t)(b0 + k) * A_TOT + p;
        __stcs(os + idx, make_float2(c0[k], c1[k]));
        __stcs(ob + idx, make_float4(y1, x1, y2, x2));
        __stcs(oa + idx, anc);
    }
}

extern "C" void kernel_launch(void* const* d_in, const int* in_sizes, int n_in,
                              void* d_out, int out_size) {
    (void)out_size;
    // Identify inputs by element count (robust to metadata ordering).
    Ptrs ptrs;
    ptrs.ih = nullptr; ptrs.iw = nullptr;
    for (int i = 0; i < n_in; ++i) {
        const long long sz = in_sizes[i];
        if (sz == 1) {
            if (!ptrs.ih) ptrs.ih = (const int*)d_in[i];
            else          ptrs.iw = (const int*)d_in[i];
            continue;
        }
        for (int l = 0; l < 5; ++l) {
            const long long hw = 65536LL >> (2 * l);
            if (sz == 16LL * 6 * hw)  ptrs.cs[l] = (const float*)d_in[i];
            if (sz == 16LL * 12 * hw) ptrs.bp[l] = (const float*)d_in[i];
        }
    }

    dim3 grid(A_TOT / TPB, B_SZ / KB);   // 1023 x 4
    aggregate_levels_kernel<<<grid, TPB>>>(ptrs, (float*)d_out);
}